// round 14
// baseline (speedup 1.0000x reference)
#include <cuda_runtime.h>
#include <cuda_fp16.h>
#include <math_constants.h>

#define DIM     2048
#define NHEADS  16
#define HD      128
#define BATCH   2
#define SEQ     4096
#define QKV_COLS (3*DIM)        // 6144
#define MROWS   (BATCH*SEQ)     // 8192

// ---------------------------------------------------------------------------
// Device-global scratch
// ---------------------------------------------------------------------------
__device__ __half g_Qp[(size_t)BATCH*NHEADS*SEQ*HD]; // pre-norm Q (fp16)
__device__ __half g_Kp[(size_t)BATCH*NHEADS*SEQ*HD]; // pre-norm K (fp16)
__device__ __half g_Qf[(size_t)BATCH*NHEADS*SEQ*HD]; // normed+rope, scaled
__device__ __half g_Kf[(size_t)BATCH*NHEADS*SEQ*HD];
__device__ __half g_Vt[(size_t)BATCH*NHEADS*HD*SEQ]; // V TRANSPOSED [bh][d][n]
__device__ __half g_xh[(size_t)MROWS*DIM];           // x (fp16)
__device__ __half g_wt[(size_t)QKV_COLS*DIM];        // W^T (fp16)

// ---------------------------------------------------------------------------
// PTX helpers (arch-neutral: mma.sync / ldmatrix / cp.async, sm_80+)
// ---------------------------------------------------------------------------
__device__ __forceinline__ unsigned smem_u32(const void* p) {
    unsigned a;
    asm("{ .reg .u64 t; cvta.to.shared.u64 t, %1; cvt.u32.u64 %0, t; }"
        : "=r"(a) : "l"(p));
    return a;
}
__device__ __forceinline__ void ldsm_x4(unsigned r[4], unsigned a) {
    asm volatile("ldmatrix.sync.aligned.m8n8.x4.shared.b16 {%0,%1,%2,%3}, [%4];"
                 : "=r"(r[0]), "=r"(r[1]), "=r"(r[2]), "=r"(r[3]) : "r"(a));
}
__device__ __forceinline__ void mma16816(float c[4], const unsigned a[4],
                                         const unsigned b[2]) {
    asm volatile(
        "mma.sync.aligned.m16n8k16.row.col.f32.f16.f16.f32 "
        "{%0,%1,%2,%3}, {%4,%5,%6,%7}, {%8,%9}, {%0,%1,%2,%3};"
        : "+f"(c[0]), "+f"(c[1]), "+f"(c[2]), "+f"(c[3])
        : "r"(a[0]), "r"(a[1]), "r"(a[2]), "r"(a[3]), "r"(b[0]), "r"(b[1]));
}
__device__ __forceinline__ unsigned pack_f16(float lo, float hi) {
    unsigned r;
    asm("cvt.rn.f16x2.f32 %0, %1, %2;" : "=r"(r) : "f"(hi), "f"(lo));
    return r;
}
__device__ __forceinline__ float ex2(float x) {
    float y;
    asm("ex2.approx.f32 %0, %1;" : "=f"(y) : "f"(x));
    return y;
}
__device__ __forceinline__ void cp16(unsigned dst, const void* src) {
    asm volatile("cp.async.cg.shared.global [%0], [%1], 16;"
                 :: "r"(dst), "l"(src));
}
#define CP_COMMIT()  asm volatile("cp.async.commit_group;" ::: "memory")
#define CP_WAIT(n)   asm volatile("cp.async.wait_group %0;" :: "n"(n) : "memory")

// ---------------------------------------------------------------------------
// Kernel 0a: convert x (fp32) to fp16
// ---------------------------------------------------------------------------
__global__ void convert_x_kernel(const float* __restrict__ x)
{
    size_t i = ((size_t)blockIdx.x * 256 + threadIdx.x) * 8;
    float4 v0 = *(const float4*)(x + i);
    float4 v1 = *(const float4*)(x + i + 4);
    uint4 o;
    o.x = pack_f16(v0.x, v0.y);
    o.y = pack_f16(v0.z, v0.w);
    o.z = pack_f16(v1.x, v1.y);
    o.w = pack_f16(v1.z, v1.w);
    *(uint4*)(g_xh + i) = o;
}

// ---------------------------------------------------------------------------
// Kernel 0b: transpose W [k][n] -> [n][k], fp16
// ---------------------------------------------------------------------------
__global__ void convert_w_kernel(const float* __restrict__ W)
{
    __shared__ float tile[32][33];
    int tx = threadIdx.x, ty = threadIdx.y;          // block (32, 8)
    int n0 = blockIdx.x * 32, k0 = blockIdx.y * 32;
#pragma unroll
    for (int r = 0; r < 4; r++) {
        int k = k0 + ty + r * 8;
        tile[ty + r * 8][tx] = W[(size_t)k * QKV_COLS + n0 + tx];
    }
    __syncthreads();
#pragma unroll
    for (int r = 0; r < 4; r++) {
        int n = n0 + ty + r * 8;
        int k = k0 + tx;
        g_wt[(size_t)n * DIM + k] = __float2half(tile[tx][ty + r * 8]);
    }
}

// ---------------------------------------------------------------------------
// Kernel 1: QKV GEMM, single-term fp16. CTA 128x256, K-chunk 64,
// 4-stage cp.async pipeline, ONE barrier per iteration. 8 warps, 2(M)x4(N)
// grid, warp tile 64x64. Epilogue: smem-staged coalesced de-interleave;
// Q/K fp16 [n][d]; V fp16 TRANSPOSED [d][n] (contiguous 256B runs/thread).
// ---------------------------------------------------------------------------
#define G_STR    144                // smem row stride bytes (64 fp16 + 16B pad)
#define G_A_ARR  (128*G_STR)        // 18432
#define G_B_ARR  (256*G_STR)        // 36864
#define G_STAGE  (G_A_ARR + G_B_ARR)       // 55296
#define GEMM_SMEM (4*G_STAGE)       // 221184
#define E_STR    260                // epilogue smem stride (floats)

__global__ __launch_bounds__(256, 1) void qkv_gemm_mma_kernel(
    const float* __restrict__ bias)
{
    extern __shared__ char smem[];
    const unsigned sbase = smem_u32(smem);
    const int tid = threadIdx.x;
    const int wid = tid >> 5, lane = tid & 31;
    const int warp_m = wid >> 2;            // 0..1 (64 rows each)
    const int warp_n = wid & 3;             // 0..3 (64 cols each)
    const int gM0 = blockIdx.y << 7;
    const int gN0 = blockIdx.x << 8;
    const int l15 = lane & 15;

    float acc[4][8][4];
#pragma unroll
    for (int i = 0; i < 4; i++)
#pragma unroll
        for (int j = 0; j < 8; j++)
#pragma unroll
            for (int e = 0; e < 4; e++) acc[i][j][e] = 0.f;

    const uint4* xh4 = (const uint4*)g_xh;
    const uint4* wt4 = (const uint4*)g_wt;

    auto stage_load = [&](int st, int it) {
        unsigned sb = sbase + st * G_STAGE;
        int k0 = it * 64;
#pragma unroll
        for (int l = 0; l < 12; l++) {
            int t = tid + (l << 8);                // 0..3071
            if (t < 1024) {                        // A
                int row = t >> 3, c4 = t & 7;
                size_t gi = (((size_t)(gM0 + row) * DIM + k0) >> 3) + c4;
                cp16(sb + row * G_STR + c4 * 16, xh4 + gi);
            } else {                               // B
                int w = t - 1024;
                int row = w >> 3, c4 = w & 7;
                size_t gi = (((size_t)(gN0 + row) * DIM + k0) >> 3) + c4;
                cp16(sb + G_A_ARR + row * G_STR + c4 * 16, wt4 + gi);
            }
        }
    };

    const int NIT = DIM / 64;        // 32
    stage_load(0, 0); CP_COMMIT();
    stage_load(1, 1); CP_COMMIT();
    stage_load(2, 2); CP_COMMIT();

    int buf = 0;
    for (int it = 0; it < NIT; ++it) {
        CP_WAIT(2);
        __syncthreads();     // stage it visible; all warps finished it-1

        // Early prefetch: buffer (buf+3)&3 held it-1, freed by the barrier.
        {
            int nb = (buf + 3) & 3;
            if (it + 3 < NIT) stage_load(nb, it + 3);
            CP_COMMIT();
        }

        unsigned sb = sbase + buf * G_STAGE;
        unsigned sA = sb, sB = sb + G_A_ARR;

#pragma unroll
        for (int ks = 0; ks < 4; ks++) {
            unsigned a4[4][4], b4[4][4];
            int acol = ks * 16 + (lane >> 4) * 8;
#pragma unroll
            for (int i = 0; i < 4; i++) {
                int arow = warp_m * 64 + i * 16 + l15;
                ldsm_x4(a4[i], sA + arow * G_STR + acol * 2);
            }
            int brow_off = (lane >> 4) * 8 + (lane & 7);
            int bcol = ks * 16 + ((lane >> 3) & 1) * 8;
#pragma unroll
            for (int jj = 0; jj < 4; jj++) {
                unsigned boff = (warp_n * 64 + jj * 16 + brow_off) * G_STR
                                + bcol * 2;
                ldsm_x4(b4[jj], sB + boff);
            }
#pragma unroll
            for (int i = 0; i < 4; i++)
#pragma unroll
                for (int jj = 0; jj < 4; jj++) {
                    mma16816(acc[i][2*jj],   a4[i], b4[jj]);
                    mma16816(acc[i][2*jj+1], a4[i], b4[jj] + 2);
                }
        }
        buf = (buf + 1) & 3;
    }

    // -------- Epilogue: smem-staged, coalesced de-interleave --------
    CP_WAIT(0);
    __syncthreads();               // pipeline fully drained, smem reusable

    float* sE = (float*)smem;      // 128 x 256 tile, stride E_STR floats
    const int gr = lane >> 2, qc = (lane & 3) * 2;
#pragma unroll
    for (int i = 0; i < 4; i++) {
#pragma unroll
        for (int j = 0; j < 8; j++) {
#pragma unroll
            for (int half = 0; half < 2; half++) {
                int row = warp_m * 64 + i * 16 + half * 8 + gr;
                int col = warp_n * 64 + j * 8 + qc;
                sE[row * E_STR + col]     = acc[i][j][half * 2];
                sE[row * E_STR + col + 1] = acc[i][j][half * 2 + 1];
            }
        }
    }
    __syncthreads();

    // thread tid -> (j, c) sorted by (j, c ascending)
    const int m = gN0 % 3;
    const int cnt0 = 85 + (m == 0 ? 1 : 0);
    const int cnt1 = 85 + (m == 1 ? 1 : 0);
    int jsel, idx;
    if (tid < cnt0)             { jsel = 0; idx = tid; }
    else if (tid < cnt0 + cnt1) { jsel = 1; idx = tid - cnt0; }
    else                        { jsel = 2; idx = tid - cnt0 - cnt1; }
    int c = gN0 + (((jsel - m) % 3) + 3) % 3 + 3 * idx;   // global col
    int cl = c - gN0;
    int h = c / 384;
    int d = (c - h * 384) / 3;                            // rem%3==jsel
    float bias_c = __ldg(bias + c);

    const int b = gM0 >> 12;
    const int n0 = gM0 & (SEQ - 1);

    if (jsel == 2) {
        // V transposed: [bh][d][n] -> this thread owns one d, 128 contiguous n
        __half* p = g_Vt + (((size_t)(b * NHEADS + h)) * HD + d) * SEQ + n0;
#pragma unroll
        for (int r0 = 0; r0 < 128; r0 += 8) {
            __half hbuf[8];
#pragma unroll
            for (int e = 0; e < 8; e++)
                hbuf[e] = __float2half(sE[(r0 + e) * E_STR + cl] + bias_c);
            *(uint4*)(p + r0) = *(uint4*)hbuf;
        }
    } else {
        size_t base = (((size_t)(b * NHEADS + h)) * SEQ + n0) * HD + d;
        __half* p = (jsel == 0) ? (g_Qp + base) : (g_Kp + base);
#pragma unroll 4
        for (int r = 0; r < 128; r++)
            p[(size_t)r * HD] = __float2half(sE[r * E_STR + cl] + bias_c);
    }
}

// ---------------------------------------------------------------------------
// Kernel 2: RMSNorm + RoPE, warp-per-row, fp16 in / fp16 out.
// Q pre-scaled by (1/sqrt(HD))*log2(e).
// ---------------------------------------------------------------------------
__global__ __launch_bounds__(256) void norm_rope_kernel(
    const float* __restrict__ rot, const float* __restrict__ qw,
    const float* __restrict__ kw)
{
    const int lane = threadIdx.x & 31;
    const int row = blockIdx.x * 8 + (threadIdx.x >> 5);
    const int n = row & (SEQ - 1);
    const size_t base = (size_t)row * HD + lane * 4;

    __half2 qh2[2], kh2[2];
    *(uint2*)qh2 = *(const uint2*)(g_Qp + base);
    *(uint2*)kh2 = *(const uint2*)(g_Kp + base);
    float2 qa = __half22float2(qh2[0]), qb = __half22float2(qh2[1]);
    float2 ka = __half22float2(kh2[0]), kb = __half22float2(kh2[1]);
    float q0v = qa.x, q1v = qa.y, q2v = qb.x, q3v = qb.y;
    float k0v = ka.x, k1v = ka.y, k2v = kb.x, k3v = kb.y;

    float q2 = q0v*q0v + q1v*q1v + q2v*q2v + q3v*q3v;
    float k2 = k0v*k0v + k1v*k1v + k2v*k2v + k3v*k3v;
#pragma unroll
    for (int off = 16; off; off >>= 1) {
        q2 += __shfl_xor_sync(0xffffffffu, q2, off);
        k2 += __shfl_xor_sync(0xffffffffu, k2, off);
    }
    float qs = rsqrtf(q2 * (1.0f / HD) + 1e-6f);
    float ks = rsqrtf(k2 * (1.0f / HD) + 1e-6f);

    float4 qwv = *(const float4*)(qw + lane * 4);
    float4 kwv = *(const float4*)(kw + lane * 4);

    float qn0 = q0v * qs * qwv.x, qn1 = q1v * qs * qwv.y;
    float qn2 = q2v * qs * qwv.z, qn3 = q3v * qs * qwv.w;
    float kn0 = k0v * ks * kwv.x, kn1 = k1v * ks * kwv.y;
    float kn2 = k2v * ks * kwv.z, kn3 = k3v * ks * kwv.w;

    const float* rp = rot + (size_t)n * 256 + lane * 8;
    float4 rA = *(const float4*)rp;
    float4 rB = *(const float4*)(rp + 4);

    const float scale = 0.08838834764831845f * 1.4426950408889634f;
    float qo0 = (rA.x * qn0 + rA.y * qn1) * scale;
    float qo1 = (rA.z * qn0 + rA.w * qn1) * scale;
    float qo2 = (rB.x * qn2 + rB.y * qn3) * scale;
    float qo3 = (rB.z * qn2 + rB.w * qn3) * scale;
    float ko0 = rA.x * kn0 + rA.y * kn1;
    float ko1 = rA.z * kn0 + rA.w * kn1;
    float ko2 = rB.x * kn2 + rB.y * kn3;
    float ko3 = rB.z * kn2 + rB.w * kn3;

    uint2 qo = make_uint2(pack_f16(qo0, qo1), pack_f16(qo2, qo3));
    uint2 ko = make_uint2(pack_f16(ko0, ko1), pack_f16(ko2, ko3));
    *(uint2*)(g_Qf + base) = qo;
    *(uint2*)(g_Kf + base) = ko;
}

// ---------------------------------------------------------------------------
// Kernel 3: Flash attention, fp16 single-term. BM=128 (8 warps), D=128.
// 128-key stages (3-stage pipeline), single BN=128 S pass per stage.
// V stored transposed [d][n] -> PV uses plain ldsm_x4 (no .trans).
// Q fragments register-resident. No-max exp2 softmax, deferred l reduction.
// ---------------------------------------------------------------------------
#define A_STR    272                 // smem row stride bytes (128 fp16 + pad)
#define A_KARR   (128*A_STR)         // 34816 (128-row K or V^T array)
#define A_STAGE  (2*A_KARR)          // K(128 keys) + V^T(128 d) = 69632
#define ATT_SMEM (3*A_STAGE)         // 208896

__global__ __launch_bounds__(256, 1) void attn_mma_kernel(float* __restrict__ out)
{
    extern __shared__ char smem[];
    const unsigned sbase = smem_u32(smem);
    const int bh = blockIdx.y;
    const int q0 = blockIdx.x << 7;          // 128 rows per CTA
    const int tid = threadIdx.x;
    const int wid = tid >> 5, lane = tid & 31;
    const int l15 = lane & 15;
    const int gr = lane >> 2, qc = (lane & 3) * 2;

    // --- Load Q tile (128 rows fp16) into stage-0 region ---
    {
        const uint4* Qf4 = (const uint4*)g_Qf;
#pragma unroll
        for (int l = 0; l < 8; l++) {
            int t = tid + (l << 8);            // 0..2047
            int row = t >> 4, c = t & 15;
            size_t gi = (((size_t)bh * SEQ + q0 + row) * HD >> 3) + c;
            cp16(sbase + row * A_STR + c * 16, Qf4 + gi);
        }
    }
    CP_COMMIT();
    CP_WAIT(0);
    __syncthreads();

    // --- Hoist Q fragments to registers (once) ---
    unsigned qf[8][4];
    {
        int arow = wid * 16 + l15;
#pragma unroll
        for (int ks = 0; ks < 8; ks++) {
            int acol = ks * 16 + (lane >> 4) * 8;
            ldsm_x4(qf[ks], sbase + arow * A_STR + acol * 2);
        }
    }
    __syncthreads();   // staging free before K/V pipeline reuses it

    const uint4* Kf4 = (const uint4*)g_Kf;
    const uint4* Vt4 = (const uint4*)g_Vt;

    // stage: K rows = 128 keys (d contiguous); V^T rows = 128 d (keys contig)
    auto stage_load = [&](int st, int kt) {
        unsigned sb = sbase + st * A_STAGE;
#pragma unroll
        for (int l = 0; l < 16; l++) {
            int t = tid + (l << 8);            // 0..4095
            int arr = t >> 11;                 // 0: K, 1: V^T
            int w = t & 2047;
            int row = w >> 4, c = w & 15;      // row 0..127
            size_t gi;
            if (arr == 0)
                gi = (((size_t)bh * SEQ + kt * 128 + row) * HD >> 3) + c;
            else
                gi = ((((size_t)bh * HD + row) * SEQ + kt * 128) >> 3) + c;
            const uint4* s = arr ? Vt4 : Kf4;
            cp16(sb + arr * A_KARR + row * A_STR + c * 16, s + gi);
        }
    };

    float O[16][4];
#pragma unroll
    for (int n = 0; n < 16; n++)
#pragma unroll
        for (int e = 0; e < 4; e++) O[n][e] = 0.f;
    float l0 = 0.f, l1 = 0.f;

    const int NKT = SEQ / 128;   // 32
    stage_load(0, 0); CP_COMMIT();
    stage_load(1, 1); CP_COMMIT();

    int buf = 0;
    for (int kt = 0; kt < NKT; kt++) {
        CP_WAIT(1);
        __syncthreads();        // stage kt visible; all warps done with kt-1

        // Early prefetch into the buffer freed at kt-1.
        {
            int nb = buf + 2; if (nb >= 3) nb -= 3;
            if (kt + 2 < NKT) stage_load(nb, kt + 2);
            CP_COMMIT();
        }

        unsigned sKf = sbase + buf * A_STAGE;
        unsigned sVt = sKf + A_KARR;

        // --- S = Q K^T over all 128 keys ---
        float S[16][4];
#pragma unroll
        for (int j = 0; j < 16; j++)
#pragma unroll
            for (int e = 0; e < 4; e++) S[j][e] = 0.f;

        const int brow_off = (lane >> 4) * 8 + (lane & 7);
        const int g_kh = ((lane >> 3) & 1) * 8;
        {
#pragma unroll
            for (int ks = 0; ks < 8; ks++) {
                int bcol = ks * 16 + g_kh;
#pragma unroll
                for (int jj = 0; jj < 8; jj++) {
                    unsigned k4[4];
                    unsigned boff = (jj * 16 + brow_off) * A_STR + bcol * 2;
                    ldsm_x4(k4, sKf + boff);
                    mma16816(S[2*jj],   qf[ks], k4);
                    mma16816(S[2*jj+1], qf[ks], k4 + 2);
                }
            }
        }

        // --- No-max softmax: P = exp2(S); accumulate partial l ---
#pragma unroll
        for (int j = 0; j < 16; j++) {
            S[j][0] = ex2(S[j][0]);
            S[j][1] = ex2(S[j][1]);
            S[j][2] = ex2(S[j][2]);
            S[j][3] = ex2(S[j][3]);
            l0 += S[j][0] + S[j][1];
            l1 += S[j][2] + S[j][3];
        }

        // --- O += P V: B-fragments from V^T via plain ldsm_x4 ---
        {
#pragma unroll
            for (int t = 0; t < 8; t++) {        // key k16 chunk
                unsigned ph[4];
                const float* s0 = S[2 * t];
                const float* s1 = S[2 * t + 1];
                ph[0] = pack_f16(s0[0], s0[1]);
                ph[1] = pack_f16(s0[2], s0[3]);
                ph[2] = pack_f16(s1[0], s1[1]);
                ph[3] = pack_f16(s1[2], s1[3]);
                int vcol = t * 16 + g_kh;        // key offset within stage
#pragma unroll
                for (int nn = 0; nn < 8; nn++) { // d chunk of 16 (two n8)
                    unsigned v4[4];
                    unsigned voff = (nn * 16 + brow_off) * A_STR + vcol * 2;
                    ldsm_x4(v4, sVt + voff);
                    mma16816(O[2*nn],   ph, v4);
                    mma16816(O[2*nn+1], ph, v4 + 2);
                }
            }
        }

        if (++buf == 3) buf = 0;
    }

    // --- Final l reduction across the 4 lanes of each row group ---
    l0 += __shfl_xor_sync(0xffffffffu, l0, 1);
    l0 += __shfl_xor_sync(0xffffffffu, l0, 2);
    l1 += __shfl_xor_sync(0xffffffffu, l1, 1);
    l1 += __shfl_xor_sync(0xffffffffu, l1, 2);

    // --- Write output ---
    const int b = bh >> 4, h = bh & 15;
    float inv0 = __fdividef(1.0f, l0);
    float inv1 = __fdividef(1.0f, l1);
    int n0g = q0 + wid * 16 + gr;
    float* o0 = out + ((size_t)b * SEQ + n0g) * DIM + h * HD;
    float* o1 = out + ((size_t)b * SEQ + n0g + 8) * DIM + h * HD;
#pragma unroll
    for (int n = 0; n < 16; n++) {
        int d = n * 8 + qc;
        float2 w0 = make_float2(O[n][0] * inv0, O[n][1] * inv0);
        float2 w1 = make_float2(O[n][2] * inv1, O[n][3] * inv1);
        *(float2*)(o0 + d) = w0;
        *(float2*)(o1 + d) = w1;
    }
}

// ---------------------------------------------------------------------------
extern "C" void kernel_launch(void* const* d_in, const int* in_sizes, int n_in,
                              void* d_out, int out_size)
{
    const float* x    = (const float*)d_in[0];
    const float* rot  = (const float*)d_in[1];
    const float* W    = (const float*)d_in[2];
    const float* bias = (const float*)d_in[3];
    const float* qw   = (const float*)d_in[4];
    const float* kw   = (const float*)d_in[5];
    float* out = (float*)d_out;

    convert_x_kernel<<<(MROWS * DIM) / (256 * 8), 256>>>(x);
    convert_w_kernel<<<dim3(QKV_COLS / 32, DIM / 32), dim3(32, 8)>>>(W);

    cudaFuncSetAttribute(qkv_gemm_mma_kernel,
                         cudaFuncAttributeMaxDynamicSharedMemorySize, GEMM_SMEM);
    qkv_gemm_mma_kernel<<<dim3(QKV_COLS / 256, MROWS / 128), 256, GEMM_SMEM>>>(bias);

    norm_rope_kernel<<<(BATCH * NHEADS * SEQ) / 8, 256>>>(rot, qw, kw);

    cudaFuncSetAttribute(attn_mma_kernel,
                         cudaFuncAttributeMaxDynamicSharedMemorySize, ATT_SMEM);
    attn_mma_kernel<<<dim3(SEQ / 128, BATCH * NHEADS), 256, ATT_SMEM>>>(out);
}

// round 16
// speedup vs baseline: 1.0318x; 1.0318x over previous
#include <cuda_runtime.h>
#include <cuda_fp16.h>
#include <math_constants.h>

#define DIM     2048
#define NHEADS  16
#define HD      128
#define BATCH   2
#define SEQ     4096
#define QKV_COLS (3*DIM)        // 6144
#define MROWS   (BATCH*SEQ)     // 8192

// ---------------------------------------------------------------------------
// Device-global scratch
// ---------------------------------------------------------------------------
__device__ __half g_Qp[(size_t)BATCH*NHEADS*SEQ*HD]; // pre-norm Q (fp16)
__device__ __half g_Kp[(size_t)BATCH*NHEADS*SEQ*HD]; // pre-norm K (fp16)
__device__ __half g_Qf[(size_t)BATCH*NHEADS*SEQ*HD]; // normed+rope, scaled
__device__ __half g_Kf[(size_t)BATCH*NHEADS*SEQ*HD];
__device__ __half g_Vf[(size_t)BATCH*NHEADS*SEQ*HD]; // V [n][d]
__device__ __half g_xh[(size_t)MROWS*DIM];           // x (fp16)
__device__ __half g_wt[(size_t)QKV_COLS*DIM];        // W^T (fp16)

// ---------------------------------------------------------------------------
// PTX helpers (arch-neutral: mma.sync / ldmatrix / cp.async, sm_80+)
// ---------------------------------------------------------------------------
__device__ __forceinline__ unsigned smem_u32(const void* p) {
    unsigned a;
    asm("{ .reg .u64 t; cvta.to.shared.u64 t, %1; cvt.u32.u64 %0, t; }"
        : "=r"(a) : "l"(p));
    return a;
}
__device__ __forceinline__ void ldsm_x4(unsigned r[4], unsigned a) {
    asm volatile("ldmatrix.sync.aligned.m8n8.x4.shared.b16 {%0,%1,%2,%3}, [%4];"
                 : "=r"(r[0]), "=r"(r[1]), "=r"(r[2]), "=r"(r[3]) : "r"(a));
}
__device__ __forceinline__ void ldsm_x4_t(unsigned r[4], unsigned a) {
    asm volatile("ldmatrix.sync.aligned.m8n8.x4.trans.shared.b16 {%0,%1,%2,%3}, [%4];"
                 : "=r"(r[0]), "=r"(r[1]), "=r"(r[2]), "=r"(r[3]) : "r"(a));
}
__device__ __forceinline__ void mma16816(float c[4], const unsigned a[4],
                                         const unsigned b[2]) {
    asm volatile(
        "mma.sync.aligned.m16n8k16.row.col.f32.f16.f16.f32 "
        "{%0,%1,%2,%3}, {%4,%5,%6,%7}, {%8,%9}, {%0,%1,%2,%3};"
        : "+f"(c[0]), "+f"(c[1]), "+f"(c[2]), "+f"(c[3])
        : "r"(a[0]), "r"(a[1]), "r"(a[2]), "r"(a[3]), "r"(b[0]), "r"(b[1]));
}
__device__ __forceinline__ unsigned pack_f16(float lo, float hi) {
    unsigned r;
    asm("cvt.rn.f16x2.f32 %0, %1, %2;" : "=r"(r) : "f"(hi), "f"(lo));
    return r;
}
__device__ __forceinline__ float ex2(float x) {
    float y;
    asm("ex2.approx.f32 %0, %1;" : "=f"(y) : "f"(x));
    return y;
}
__device__ __forceinline__ void cp16(unsigned dst, const void* src) {
    asm volatile("cp.async.cg.shared.global [%0], [%1], 16;"
                 :: "r"(dst), "l"(src));
}
#define CP_COMMIT()  asm volatile("cp.async.commit_group;" ::: "memory")
#define CP_WAIT(n)   asm volatile("cp.async.wait_group %0;" :: "n"(n) : "memory")

// ---------------------------------------------------------------------------
// Kernel 0a: convert x (fp32) to fp16
// ---------------------------------------------------------------------------
__global__ void convert_x_kernel(const float* __restrict__ x)
{
    size_t i = ((size_t)blockIdx.x * 256 + threadIdx.x) * 8;
    float4 v0 = *(const float4*)(x + i);
    float4 v1 = *(const float4*)(x + i + 4);
    uint4 o;
    o.x = pack_f16(v0.x, v0.y);
    o.y = pack_f16(v0.z, v0.w);
    o.z = pack_f16(v1.x, v1.y);
    o.w = pack_f16(v1.z, v1.w);
    *(uint4*)(g_xh + i) = o;
}

// ---------------------------------------------------------------------------
// Kernel 0b: transpose W [k][n] -> [n][k], fp16
// ---------------------------------------------------------------------------
__global__ void convert_w_kernel(const float* __restrict__ W)
{
    __shared__ float tile[32][33];
    int tx = threadIdx.x, ty = threadIdx.y;          // block (32, 8)
    int n0 = blockIdx.x * 32, k0 = blockIdx.y * 32;
#pragma unroll
    for (int r = 0; r < 4; r++) {
        int k = k0 + ty + r * 8;
        tile[ty + r * 8][tx] = W[(size_t)k * QKV_COLS + n0 + tx];
    }
    __syncthreads();
#pragma unroll
    for (int r = 0; r < 4; r++) {
        int n = n0 + ty + r * 8;
        int k = k0 + tx;
        g_wt[(size_t)n * DIM + k] = __float2half(tile[tx][ty + r * 8]);
    }
}

// ---------------------------------------------------------------------------
// Kernel 1: QKV GEMM, single-term fp16. CTA 128x256, K-chunk 64,
// 4-stage cp.async pipeline, ONE barrier per iteration. 8 warps, 2(M)x4(N)
// grid, warp tile 64x64. Epilogue: smem-staged coalesced de-interleave.
// ---------------------------------------------------------------------------
#define G_STR    144                // smem row stride bytes (64 fp16 + 16B pad)
#define G_A_ARR  (128*G_STR)        // 18432
#define G_B_ARR  (256*G_STR)        // 36864
#define G_STAGE  (G_A_ARR + G_B_ARR)       // 55296
#define GEMM_SMEM (4*G_STAGE)       // 221184
#define E_STR    260                // epilogue smem stride (floats)

__global__ __launch_bounds__(256, 1) void qkv_gemm_mma_kernel(
    const float* __restrict__ bias)
{
    extern __shared__ char smem[];
    const unsigned sbase = smem_u32(smem);
    const int tid = threadIdx.x;
    const int wid = tid >> 5, lane = tid & 31;
    const int warp_m = wid >> 2;            // 0..1 (64 rows each)
    const int warp_n = wid & 3;             // 0..3 (64 cols each)
    const int gM0 = blockIdx.y << 7;
    const int gN0 = blockIdx.x << 8;
    const int l15 = lane & 15;

    float acc[4][8][4];
#pragma unroll
    for (int i = 0; i < 4; i++)
#pragma unroll
        for (int j = 0; j < 8; j++)
#pragma unroll
            for (int e = 0; e < 4; e++) acc[i][j][e] = 0.f;

    const uint4* xh4 = (const uint4*)g_xh;
    const uint4* wt4 = (const uint4*)g_wt;

    auto stage_load = [&](int st, int it) {
        unsigned sb = sbase + st * G_STAGE;
        int k0 = it * 64;
#pragma unroll
        for (int l = 0; l < 12; l++) {
            int t = tid + (l << 8);                // 0..3071
            if (t < 1024) {                        // A
                int row = t >> 3, c4 = t & 7;
                size_t gi = (((size_t)(gM0 + row) * DIM + k0) >> 3) + c4;
                cp16(sb + row * G_STR + c4 * 16, xh4 + gi);
            } else {                               // B
                int w = t - 1024;
                int row = w >> 3, c4 = w & 7;
                size_t gi = (((size_t)(gN0 + row) * DIM + k0) >> 3) + c4;
                cp16(sb + G_A_ARR + row * G_STR + c4 * 16, wt4 + gi);
            }
        }
    };

    const int NIT = DIM / 64;        // 32
    stage_load(0, 0); CP_COMMIT();
    stage_load(1, 1); CP_COMMIT();
    stage_load(2, 2); CP_COMMIT();

    int buf = 0;
    for (int it = 0; it < NIT; ++it) {
        CP_WAIT(2);
        __syncthreads();     // stage it visible; all warps finished it-1

        // Early prefetch: buffer (buf+3)&3 held it-1, freed by the barrier.
        {
            int nb = (buf + 3) & 3;
            if (it + 3 < NIT) stage_load(nb, it + 3);
            CP_COMMIT();
        }

        unsigned sb = sbase + buf * G_STAGE;
        unsigned sA = sb, sB = sb + G_A_ARR;

#pragma unroll
        for (int ks = 0; ks < 4; ks++) {
            unsigned a4[4][4], b4[4][4];
            int acol = ks * 16 + (lane >> 4) * 8;
#pragma unroll
            for (int i = 0; i < 4; i++) {
                int arow = warp_m * 64 + i * 16 + l15;
                ldsm_x4(a4[i], sA + arow * G_STR + acol * 2);
            }
            int brow_off = (lane >> 4) * 8 + (lane & 7);
            int bcol = ks * 16 + ((lane >> 3) & 1) * 8;
#pragma unroll
            for (int jj = 0; jj < 4; jj++) {
                unsigned boff = (warp_n * 64 + jj * 16 + brow_off) * G_STR
                                + bcol * 2;
                ldsm_x4(b4[jj], sB + boff);
            }
#pragma unroll
            for (int i = 0; i < 4; i++)
#pragma unroll
                for (int jj = 0; jj < 4; jj++) {
                    mma16816(acc[i][2*jj],   a4[i], b4[jj]);
                    mma16816(acc[i][2*jj+1], a4[i], b4[jj] + 2);
                }
        }
        buf = (buf + 1) & 3;
    }

    // -------- Epilogue: smem-staged, coalesced de-interleave --------
    CP_WAIT(0);
    __syncthreads();               // pipeline fully drained, smem reusable

    float* sE = (float*)smem;      // 128 x 256 tile, stride E_STR floats
    const int gr = lane >> 2, qc = (lane & 3) * 2;
#pragma unroll
    for (int i = 0; i < 4; i++) {
#pragma unroll
        for (int j = 0; j < 8; j++) {
#pragma unroll
            for (int half = 0; half < 2; half++) {
                int row = warp_m * 64 + i * 16 + half * 8 + gr;
                int col = warp_n * 64 + j * 8 + qc;
                sE[row * E_STR + col]     = acc[i][j][half * 2];
                sE[row * E_STR + col + 1] = acc[i][j][half * 2 + 1];
            }
        }
    }
    __syncthreads();

    // thread tid -> (j, c) sorted by (j, c ascending)
    const int m = gN0 % 3;
    const int cnt0 = 85 + (m == 0 ? 1 : 0);
    const int cnt1 = 85 + (m == 1 ? 1 : 0);
    int jsel, idx;
    if (tid < cnt0)             { jsel = 0; idx = tid; }
    else if (tid < cnt0 + cnt1) { jsel = 1; idx = tid - cnt0; }
    else                        { jsel = 2; idx = tid - cnt0 - cnt1; }
    int c = gN0 + (((jsel - m) % 3) + 3) % 3 + 3 * idx;   // global col
    int cl = c - gN0;
    int h = c / 384;
    int d = (c - h * 384) / 3;                            // rem%3==jsel
    float bias_c = __ldg(bias + c);

    const int b = gM0 >> 12;
    const int n0 = gM0 & (SEQ - 1);
    size_t base = (((size_t)(b * NHEADS + h)) * SEQ + n0) * HD + d;

    __half* p = (jsel == 0) ? (g_Qp + base)
              : (jsel == 1) ? (g_Kp + base) : (g_Vf + base);
#pragma unroll 4
    for (int r = 0; r < 128; r++)
        p[(size_t)r * HD] = __float2half(sE[r * E_STR + cl] + bias_c);
}

// ---------------------------------------------------------------------------
// Kernel 2: RMSNorm + RoPE, warp-per-row, fp16 in / fp16 out.
// Q pre-scaled by (1/sqrt(HD))*log2(e).
// ---------------------------------------------------------------------------
__global__ __launch_bounds__(256) void norm_rope_kernel(
    const float* __restrict__ rot, const float* __restrict__ qw,
    const float* __restrict__ kw)
{
    const int lane = threadIdx.x & 31;
    const int row = blockIdx.x * 8 + (threadIdx.x >> 5);
    const int n = row & (SEQ - 1);
    const size_t base = (size_t)row * HD + lane * 4;

    __half2 qh2[2], kh2[2];
    *(uint2*)qh2 = *(const uint2*)(g_Qp + base);
    *(uint2*)kh2 = *(const uint2*)(g_Kp + base);
    float2 qa = __half22float2(qh2[0]), qb = __half22float2(qh2[1]);
    float2 ka = __half22float2(kh2[0]), kb = __half22float2(kh2[1]);
    float q0v = qa.x, q1v = qa.y, q2v = qb.x, q3v = qb.y;
    float k0v = ka.x, k1v = ka.y, k2v = kb.x, k3v = kb.y;

    float q2 = q0v*q0v + q1v*q1v + q2v*q2v + q3v*q3v;
    float k2 = k0v*k0v + k1v*k1v + k2v*k2v + k3v*k3v;
#pragma unroll
    for (int off = 16; off; off >>= 1) {
        q2 += __shfl_xor_sync(0xffffffffu, q2, off);
        k2 += __shfl_xor_sync(0xffffffffu, k2, off);
    }
    float qs = rsqrtf(q2 * (1.0f / HD) + 1e-6f);
    float ks = rsqrtf(k2 * (1.0f / HD) + 1e-6f);

    float4 qwv = *(const float4*)(qw + lane * 4);
    float4 kwv = *(const float4*)(kw + lane * 4);

    float qn0 = q0v * qs * qwv.x, qn1 = q1v * qs * qwv.y;
    float qn2 = q2v * qs * qwv.z, qn3 = q3v * qs * qwv.w;
    float kn0 = k0v * ks * kwv.x, kn1 = k1v * ks * kwv.y;
    float kn2 = k2v * ks * kwv.z, kn3 = k3v * ks * kwv.w;

    const float* rp = rot + (size_t)n * 256 + lane * 8;
    float4 rA = *(const float4*)rp;
    float4 rB = *(const float4*)(rp + 4);

    const float scale = 0.08838834764831845f * 1.4426950408889634f;
    float qo0 = (rA.x * qn0 + rA.y * qn1) * scale;
    float qo1 = (rA.z * qn0 + rA.w * qn1) * scale;
    float qo2 = (rB.x * qn2 + rB.y * qn3) * scale;
    float qo3 = (rB.z * qn2 + rB.w * qn3) * scale;
    float ko0 = rA.x * kn0 + rA.y * kn1;
    float ko1 = rA.z * kn0 + rA.w * kn1;
    float ko2 = rB.x * kn2 + rB.y * kn3;
    float ko3 = rB.z * kn2 + rB.w * kn3;

    uint2 qo = make_uint2(pack_f16(qo0, qo1), pack_f16(qo2, qo3));
    uint2 ko = make_uint2(pack_f16(ko0, ko1), pack_f16(ko2, ko3));
    *(uint2*)(g_Qf + base) = qo;
    *(uint2*)(g_Kf + base) = ko;
}

// ---------------------------------------------------------------------------
// Kernel 3: Flash attention, fp16 single-term. BM=128, 8 warps in a
// 4(M)x2(keys) grid: warp = 32 q-rows x 64 keys. Each K/V fragment feeds
// 4 mma; ldsm:mma = 3.2:1 (matches GEMM). Q persistent in smem, re-read
// per stage. No-max exp2 softmax => O and l additive across key halves;
// partial O/l reduced once via smem at the end. 2-stage 128-key pipeline.
// V fragment addressing copied verbatim from the R13 kernel (vrow_off /
// vcol_off), only the key base is offset by wk*64.
// ---------------------------------------------------------------------------
#define A_STR    272                 // smem row stride bytes (128 fp16 + pad)
#define A_QARR   (128*A_STR)         // 34816 (persistent Q tile)
#define A_KARR   (128*A_STR)         // 34816 (128-key K or V array)
#define A_STAGE  (2*A_KARR)          // 69632
#define ATT_SMEM (A_QARR + 2*A_STAGE)   // 174080
#define R_STR    132                 // O-reduction smem stride (floats)

__global__ __launch_bounds__(256, 1) void attn_mma_kernel(float* __restrict__ out)
{
    extern __shared__ char smem[];
    const unsigned sbase = smem_u32(smem);
    const int bh = blockIdx.y;
    const int q0 = blockIdx.x << 7;          // 128 rows per CTA
    const int tid = threadIdx.x;
    const int wid = tid >> 5, lane = tid & 31;
    const int wm = wid >> 1;                 // 0..3 : 32 q-rows each
    const int wk = wid & 1;                  // 0..1 : 64-key half
    const int l15 = lane & 15;
    const int gr = lane >> 2, qc = (lane & 3) * 2;
    const int brow_off = (lane >> 4) * 8 + (lane & 7);
    const int g_kh = ((lane >> 3) & 1) * 8;
    const int vrow_off = (((lane >> 3) & 1) * 8) + (lane & 7);   // R13 layout
    const int vcol_off = (lane >> 4) * 16;                       // R13 layout

    // --- Load Q tile (128 rows fp16) into persistent region ---
    {
        const uint4* Qf4 = (const uint4*)g_Qf;
#pragma unroll
        for (int l = 0; l < 8; l++) {
            int t = tid + (l << 8);            // 0..2047
            int row = t >> 4, c = t & 15;
            size_t gi = (((size_t)bh * SEQ + q0 + row) * HD >> 3) + c;
            cp16(sbase + row * A_STR + c * 16, Qf4 + gi);
        }
    }
    CP_COMMIT();

    const uint4* Kf4 = (const uint4*)g_Kf;
    const uint4* Vf4 = (const uint4*)g_Vf;

    // stage = 128 keys: K rows 0..127 then V rows 0..127
    auto stage_load = [&](int st, int kt) {
        unsigned sb = sbase + A_QARR + st * A_STAGE;
#pragma unroll
        for (int l = 0; l < 16; l++) {
            int t = tid + (l << 8);            // 0..4095
            int arr = t >> 11;                 // 0: K, 1: V
            int w = t & 2047;
            int row = w >> 4, c = w & 15;      // row 0..127
            size_t gi = (((size_t)bh * SEQ + kt * 128 + row) * HD >> 3) + c;
            const uint4* s = arr ? Vf4 : Kf4;
            cp16(sb + arr * A_KARR + row * A_STR + c * 16, s + gi);
        }
    };

    float O[2][16][4];
#pragma unroll
    for (int m = 0; m < 2; m++)
#pragma unroll
        for (int n = 0; n < 16; n++)
#pragma unroll
            for (int e = 0; e < 4; e++) O[m][n][e] = 0.f;
    float lp[4] = {0.f, 0.f, 0.f, 0.f};

    const int NKT = SEQ / 128;   // 32
    stage_load(0, 0); CP_COMMIT();
    stage_load(1, 1); CP_COMMIT();

    for (int kt = 0; kt < NKT; kt++) {
        CP_WAIT(1);
        __syncthreads();        // stage kt visible

        unsigned sK = sbase + A_QARR + (kt & 1) * A_STAGE;
        unsigned sV = sK + A_KARR;

        // --- S = Q K^T : 32 q-rows x 64 keys per warp ---
        float S[2][8][4];
#pragma unroll
        for (int m = 0; m < 2; m++)
#pragma unroll
            for (int j = 0; j < 8; j++)
#pragma unroll
                for (int e = 0; e < 4; e++) S[m][j][e] = 0.f;

#pragma unroll
        for (int ks = 0; ks < 8; ks++) {
            unsigned qa[2][4];
            int acol = ks * 16 + (lane >> 4) * 8;
#pragma unroll
            for (int m = 0; m < 2; m++)
                ldsm_x4(qa[m],
                        sbase + (wm * 32 + m * 16 + l15) * A_STR + acol * 2);
            int bcol = ks * 16 + g_kh;
#pragma unroll
            for (int jj = 0; jj < 4; jj++) {
                unsigned k4[4];
                unsigned boff = (wk * 64 + jj * 16 + brow_off) * A_STR
                                + bcol * 2;
                ldsm_x4(k4, sK + boff);
#pragma unroll
                for (int m = 0; m < 2; m++) {
                    mma16816(S[m][2*jj],   qa[m], k4);
                    mma16816(S[m][2*jj+1], qa[m], k4 + 2);
                }
            }
        }

        // --- P = exp2(S); partial l ---
#pragma unroll
        for (int m = 0; m < 2; m++)
#pragma unroll
            for (int j = 0; j < 8; j++) {
                S[m][j][0] = ex2(S[m][j][0]);
                S[m][j][1] = ex2(S[m][j][1]);
                S[m][j][2] = ex2(S[m][j][2]);
                S[m][j][3] = ex2(S[m][j][3]);
                lp[2*m]   += S[m][j][0] + S[m][j][1];
                lp[2*m+1] += S[m][j][2] + S[m][j][3];
            }

        // --- O += P V over this warp's 64 keys (R13 addressing + wk*64) ---
#pragma unroll
        for (int t = 0; t < 4; t++) {
            unsigned ph[2][4];
#pragma unroll
            for (int m = 0; m < 2; m++) {
                const float* s0 = S[m][2*t];
                const float* s1 = S[m][2*t+1];
                ph[m][0] = pack_f16(s0[0], s0[1]);
                ph[m][1] = pack_f16(s0[2], s0[3]);
                ph[m][2] = pack_f16(s1[0], s1[1]);
                ph[m][3] = pack_f16(s1[2], s1[3]);
            }
#pragma unroll
            for (int nn = 0; nn < 8; nn++) {
                unsigned v4[4];
                unsigned va = (wk * 64 + t * 16 + vrow_off) * A_STR
                              + nn * 32 + vcol_off;
                ldsm_x4_t(v4, sV + va);
#pragma unroll
                for (int m = 0; m < 2; m++) {
                    mma16816(O[m][2*nn],   ph[m], v4);
                    mma16816(O[m][2*nn+1], ph[m], v4 + 2);
                }
            }
        }

        __syncthreads();        // all warps done with stage before refill
        if (kt + 2 < NKT) stage_load(kt & 1, kt + 2);
        CP_COMMIT();
    }

    // --- l: reduce within lane quads ---
#pragma unroll
    for (int i = 0; i < 4; i++) {
        lp[i] += __shfl_xor_sync(0xffffffffu, lp[i], 1);
        lp[i] += __shfl_xor_sync(0xffffffffu, lp[i], 2);
    }

    // --- Cross-key-half reduction via smem (O, l additive: no-max) ---
    CP_WAIT(0);
    __syncthreads();
    float* sO = (float*)(smem + A_QARR);      // [128][R_STR]
    float* sL = sO + 128 * R_STR;             // 128 floats

    if (wk == 1) {
#pragma unroll
        for (int m = 0; m < 2; m++) {
            int row = wm * 32 + m * 16 + gr;
#pragma unroll
            for (int n = 0; n < 16; n++) {
                sO[row * R_STR + n * 8 + qc]           = O[m][n][0];
                sO[row * R_STR + n * 8 + qc + 1]       = O[m][n][1];
                sO[(row + 8) * R_STR + n * 8 + qc]     = O[m][n][2];
                sO[(row + 8) * R_STR + n * 8 + qc + 1] = O[m][n][3];
            }
            if ((lane & 3) == 0) {
                sL[row]     = lp[2*m];
                sL[row + 8] = lp[2*m+1];
            }
        }
    }
    __syncthreads();

    if (wk == 0) {
        const int b = bh >> 4, h = bh & 15;
#pragma unroll
        for (int m = 0; m < 2; m++) {
            int row = wm * 32 + m * 16 + gr;
            float inv0 = __fdividef(1.0f, lp[2*m]   + sL[row]);
            float inv1 = __fdividef(1.0f, lp[2*m+1] + sL[row + 8]);
            int n0g = q0 + row;
            float* o0 = out + ((size_t)b * SEQ + n0g) * DIM + h * HD;
            float* o1 = out + ((size_t)b * SEQ + n0g + 8) * DIM + h * HD;
#pragma unroll
            for (int n = 0; n < 16; n++) {
                int d = n * 8 + qc;
                float2 w0 = make_float2(
                    (O[m][n][0] + sO[row * R_STR + d])     * inv0,
                    (O[m][n][1] + sO[row * R_STR + d + 1]) * inv0);
                float2 w1 = make_float2(
                    (O[m][n][2] + sO[(row + 8) * R_STR + d])     * inv1,
                    (O[m][n][3] + sO[(row + 8) * R_STR + d + 1]) * inv1);
                *(float2*)(o0 + d) = w0;
                *(float2*)(o1 + d) = w1;
            }
        }
    }
}

// ---------------------------------------------------------------------------
extern "C" void kernel_launch(void* const* d_in, const int* in_sizes, int n_in,
                              void* d_out, int out_size)
{
    const float* x    = (const float*)d_in[0];
    const float* rot  = (const float*)d_in[1];
    const float* W    = (const float*)d_in[2];
    const float* bias = (const float*)d_in[3];
    const float* qw   = (const float*)d_in[4];
    const float* kw   = (const float*)d_in[5];
    float* out = (float*)d_out;

    convert_x_kernel<<<(MROWS * DIM) / (256 * 8), 256>>>(x);
    convert_w_kernel<<<dim3(QKV_COLS / 32, DIM / 32), dim3(32, 8)>>>(W);

    cudaFuncSetAttribute(qkv_gemm_mma_kernel,
                         cudaFuncAttributeMaxDynamicSharedMemorySize, GEMM_SMEM);
    qkv_gemm_mma_kernel<<<dim3(QKV_COLS / 256, MROWS / 128), 256, GEMM_SMEM>>>(bias);

    norm_rope_kernel<<<(BATCH * NHEADS * SEQ) / 8, 256>>>(rot, qw, kw);

    cudaFuncSetAttribute(attn_mma_kernel,
                         cudaFuncAttributeMaxDynamicSharedMemorySize, ATT_SMEM);
    attn_mma_kernel<<<dim3(SEQ / 128, BATCH * NHEADS), 256, ATT_SMEM>>>(out);
}